// round 1
// baseline (speedup 1.0000x reference)
#include <cuda_runtime.h>
#include <math.h>
#include <stdint.h>

#define Bsz   64
#define Ssz   2048
#define ENCd  512
#define ATTNd 256

#define TILE_S   128
#define KC       16
#define A_STRIDE 20     // bank map (20*r+k)%32 = (4r+k)%32 -> 32 distinct for r in 0..7, k in 0..3
#define B_STRIDE 264    // bank map (264*k+n)%32 = (8k+n)%32 -> 32 distinct for k in 0..3, n(gid) in 0..7

__device__ float g_dec_proj[Bsz * ATTNd];
__device__ float g_scores[Bsz * Ssz];

__device__ __forceinline__ uint32_t f2tf32(float f) {
    uint32_t r;
    asm("cvt.rna.tf32.f32 %0, %1;" : "=r"(r) : "f"(f));
    return r;
}

__device__ __forceinline__ void mma_tf32(float c[4],
                                         uint32_t a0, uint32_t a1, uint32_t a2, uint32_t a3,
                                         uint32_t b0, uint32_t b1) {
    asm volatile(
        "mma.sync.aligned.m16n8k8.row.col.f32.tf32.tf32.f32 "
        "{%0,%1,%2,%3}, {%4,%5,%6,%7}, {%8,%9}, {%0,%1,%2,%3};"
        : "+f"(c[0]), "+f"(c[1]), "+f"(c[2]), "+f"(c[3])
        : "r"(a0), "r"(a1), "r"(a2), "r"(a3), "r"(b0), "r"(b1));
}

// ---------------------------------------------------------------------------
// Kernel 0: dec_proj[b,n] = sum_d dec_state[b,d] * W_dec[d,n]
// ---------------------------------------------------------------------------
__global__ __launch_bounds__(256) void dec_proj_kernel(const float* __restrict__ dec_state,
                                                       const float* __restrict__ W_dec) {
    int b = blockIdx.x;
    int n = threadIdx.x;  // 0..255
    __shared__ float ds[ENCd];
    for (int i = threadIdx.x; i < ENCd; i += 256) ds[i] = dec_state[b * ENCd + i];
    __syncthreads();
    float acc = 0.f;
#pragma unroll 8
    for (int d = 0; d < ENCd; d++) acc += ds[d] * W_dec[d * ATTNd + n];
    g_dec_proj[b * ATTNd + n] = acc;
}

// ---------------------------------------------------------------------------
// Kernel 1: scores[b,s] = sum_n v[n] * tanh( (enc[b] @ W_enc)[s,n] + dec_proj[b,n] )
// TF32 mma.sync, CTA tile 128(S) x 256(N), K staged in 16-wide chunks.
// 8 warps laid out 2(m) x 4(n); per warp: 4 m-tiles(16) x 8 n-tiles(8) = 128 fp32 acc.
// ---------------------------------------------------------------------------
__global__ __launch_bounds__(256, 1) void scores_kernel(const float* __restrict__ enc,
                                                        const float* __restrict__ W_enc,
                                                        const float* __restrict__ v) {
    __shared__ uint32_t Asm[TILE_S * A_STRIDE];   // 10240 B
    __shared__ uint32_t Bsm[KC * B_STRIDE];       // 16896 B
    __shared__ float dp_sm[ATTNd];
    __shared__ float v_sm[ATTNd];
    __shared__ float red[TILE_S * 4];

    const int tid = threadIdx.x;
    const int b = blockIdx.y;
    const int s0 = blockIdx.x * TILE_S;
    const int warp = tid >> 5, lane = tid & 31;
    const int gid = lane >> 2, tig = lane & 3;
    const int warp_m = warp >> 2, warp_n = warp & 3;
    const int m_base = warp_m * 64, n_base = warp_n * 64;

    dp_sm[tid] = g_dec_proj[b * ATTNd + tid];
    v_sm[tid] = v[tid];

    float acc[4][8][4];
#pragma unroll
    for (int mt = 0; mt < 4; mt++)
#pragma unroll
        for (int nt = 0; nt < 8; nt++)
#pragma unroll
            for (int i = 0; i < 4; i++) acc[mt][nt][i] = 0.f;

    const float* encb = enc + ((size_t)b * Ssz + s0) * ENCd;

    for (int k0 = 0; k0 < ENCd; k0 += KC) {
        __syncthreads();
        // Stage A: 128 rows x 16 k  (2 float4 per thread), convert to tf32 once here.
#pragma unroll
        for (int i = 0; i < 2; i++) {
            int idx = tid + i * 256;       // 0..511
            int row = idx >> 2;            // 0..127
            int kq = idx & 3;              // float4 index within 16-wide row
            float4 f = *reinterpret_cast<const float4*>(encb + (size_t)row * ENCd + k0 + kq * 4);
            uint4 u;
            u.x = f2tf32(f.x); u.y = f2tf32(f.y); u.z = f2tf32(f.z); u.w = f2tf32(f.w);
            *reinterpret_cast<uint4*>(&Asm[row * A_STRIDE + kq * 4]) = u;
        }
        // Stage B: 16 k-rows x 256 n  (4 float4 per thread)
#pragma unroll
        for (int i = 0; i < 4; i++) {
            int idx = tid + i * 256;       // 0..1023
            int krow = idx >> 6;           // 0..15
            int cq = idx & 63;             // float4 index within 256-wide row
            float4 f = *reinterpret_cast<const float4*>(W_enc + (size_t)(k0 + krow) * ATTNd + cq * 4);
            uint4 u;
            u.x = f2tf32(f.x); u.y = f2tf32(f.y); u.z = f2tf32(f.z); u.w = f2tf32(f.w);
            *reinterpret_cast<uint4*>(&Bsm[krow * B_STRIDE + cq * 4]) = u;
        }
        __syncthreads();

#pragma unroll
        for (int kk = 0; kk < KC; kk += 8) {
            uint32_t bf[8][2];
#pragma unroll
            for (int nt = 0; nt < 8; nt++) {
                int n = n_base + nt * 8 + gid;
                bf[nt][0] = Bsm[(kk + tig) * B_STRIDE + n];
                bf[nt][1] = Bsm[(kk + tig + 4) * B_STRIDE + n];
            }
#pragma unroll
            for (int mt = 0; mt < 4; mt++) {
                int r = m_base + mt * 16 + gid;
                uint32_t a0 = Asm[r * A_STRIDE + kk + tig];
                uint32_t a1 = Asm[(r + 8) * A_STRIDE + kk + tig];
                uint32_t a2 = Asm[r * A_STRIDE + kk + tig + 4];
                uint32_t a3 = Asm[(r + 8) * A_STRIDE + kk + tig + 4];
#pragma unroll
                for (int nt = 0; nt < 8; nt++)
                    mma_tf32(acc[mt][nt], a0, a1, a2, a3, bf[nt][0], bf[nt][1]);
            }
        }
    }

    // Epilogue: tanh(acc + dec_proj) * v, reduce over N.
    // C frag: c0=(gid, tig*2) c1=(gid, tig*2+1) c2=(gid+8, tig*2) c3=(gid+8, tig*2+1)
    float rowsum[8];
#pragma unroll
    for (int i = 0; i < 8; i++) rowsum[i] = 0.f;
#pragma unroll
    for (int mt = 0; mt < 4; mt++)
#pragma unroll
        for (int nt = 0; nt < 8; nt++) {
            int c0 = n_base + nt * 8 + tig * 2;
#pragma unroll
            for (int i = 0; i < 2; i++)
#pragma unroll
                for (int j = 0; j < 2; j++) {
                    int col = c0 + j;
                    rowsum[mt * 2 + i] +=
                        tanhf(acc[mt][nt][i * 2 + j] + dp_sm[col]) * v_sm[col];
                }
        }
    // reduce across the 4 threads of each quad (they hold disjoint columns of the same row)
#pragma unroll
    for (int i = 0; i < 8; i++) {
        rowsum[i] += __shfl_xor_sync(0xffffffff, rowsum[i], 1);
        rowsum[i] += __shfl_xor_sync(0xffffffff, rowsum[i], 2);
    }
    __syncthreads();
    if (tig == 0) {
#pragma unroll
        for (int mt = 0; mt < 4; mt++)
#pragma unroll
            for (int i = 0; i < 2; i++) {
                int row = m_base + mt * 16 + gid + 8 * i;
                red[row * 4 + warp_n] = rowsum[mt * 2 + i];
            }
    }
    __syncthreads();
    if (tid < TILE_S) {
        float s = red[tid * 4] + red[tid * 4 + 1] + red[tid * 4 + 2] + red[tid * 4 + 3];
        g_scores[b * Ssz + s0 + tid] = s;
    }
}

// ---------------------------------------------------------------------------
// Kernel 2: softmax over S per batch row -> attn region of d_out
// ---------------------------------------------------------------------------
__global__ __launch_bounds__(256) void softmax_kernel(float* __restrict__ attn_out) {
    int b = blockIdx.x;
    int tid = threadIdx.x;
    __shared__ float rbuf[256];

    float vals[8];
    float lmax = -1e30f;
#pragma unroll
    for (int i = 0; i < 8; i++) {
        float x = g_scores[b * Ssz + tid + i * 256];
        vals[i] = x;
        lmax = fmaxf(lmax, x);
    }
    rbuf[tid] = lmax;
    __syncthreads();
    for (int off = 128; off; off >>= 1) {
        if (tid < off) rbuf[tid] = fmaxf(rbuf[tid], rbuf[tid + off]);
        __syncthreads();
    }
    float m = rbuf[0];
    __syncthreads();

    float lsum = 0.f;
#pragma unroll
    for (int i = 0; i < 8; i++) {
        float e = expf(vals[i] - m);
        vals[i] = e;
        lsum += e;
    }
    rbuf[tid] = lsum;
    __syncthreads();
    for (int off = 128; off; off >>= 1) {
        if (tid < off) rbuf[tid] += rbuf[tid + off];
        __syncthreads();
    }
    float inv = 1.f / rbuf[0];
#pragma unroll
    for (int i = 0; i < 8; i++)
        attn_out[b * Ssz + tid + i * 256] = vals[i] * inv;
}

// ---------------------------------------------------------------------------
// Kernel 3: context[b,e] = sum_s attn[b,s] * enc[b,s,e]
// ---------------------------------------------------------------------------
__global__ __launch_bounds__(256) void context_kernel(const float* __restrict__ enc,
                                                      const float* __restrict__ attn,
                                                      float* __restrict__ ctx_out) {
    int b = blockIdx.y;
    int e = blockIdx.x * 256 + threadIdx.x;
    __shared__ float wsm[256];
    const float* encb = enc + (size_t)b * Ssz * ENCd;
    float acc = 0.f;
    for (int sb = 0; sb < Ssz; sb += 256) {
        __syncthreads();
        wsm[threadIdx.x] = attn[b * Ssz + sb + threadIdx.x];
        __syncthreads();
#pragma unroll 8
        for (int s = 0; s < 256; s++)
            acc += wsm[s] * encb[(size_t)(sb + s) * ENCd + e];
    }
    ctx_out[b * ENCd + e] = acc;
}

// ---------------------------------------------------------------------------
extern "C" void kernel_launch(void* const* d_in, const int* in_sizes, int n_in,
                              void* d_out, int out_size) {
    const float* enc       = (const float*)d_in[0];
    const float* dec_state = (const float*)d_in[1];
    const float* W_enc     = (const float*)d_in[2];
    const float* W_dec     = (const float*)d_in[3];
    const float* v         = (const float*)d_in[4];

    float* out  = (float*)d_out;
    float* ctx  = out;                   // [64,512]
    float* attn = out + Bsz * ENCd;      // [64,2048]

    dec_proj_kernel<<<Bsz, 256>>>(dec_state, W_dec);

    dim3 g1(Ssz / TILE_S, Bsz);
    scores_kernel<<<g1, 256>>>(enc, W_enc, v);

    softmax_kernel<<<Bsz, 256>>>(attn);

    dim3 g3(ENCd / 256, Bsz);
    context_kernel<<<g3, 256>>>(enc, attn, ctx);
}

// round 2
// speedup vs baseline: 1.4415x; 1.4415x over previous
#include <cuda_runtime.h>
#include <math.h>
#include <stdint.h>

#define Bsz   64
#define Ssz   2048
#define ENCd  512
#define ATTNd 256

#define TILE_S   128
#define KC       16
#define A_STRIDE 20     // bank map (20*r+k)%32 = (4r+k)%32 -> conflict-free
#define B_STRIDE 264    // bank map (264*k+n)%32 = (8k+n)%32 -> conflict-free

#define CSPLIT 16       // context S-splits

__device__ float g_dec_proj[Bsz * ATTNd];
__device__ float g_scores[Bsz * Ssz];
__device__ float g_ctx_part[CSPLIT * Bsz * ENCd];   // 2 MB scratch

__device__ __forceinline__ uint32_t f2tf32(float f) {
    uint32_t r;
    asm("cvt.rna.tf32.f32 %0, %1;" : "=r"(r) : "f"(f));
    return r;
}

__device__ __forceinline__ void mma_tf32(float c[4],
                                         uint32_t a0, uint32_t a1, uint32_t a2, uint32_t a3,
                                         uint32_t b0, uint32_t b1) {
    asm volatile(
        "mma.sync.aligned.m16n8k8.row.col.f32.tf32.tf32.f32 "
        "{%0,%1,%2,%3}, {%4,%5,%6,%7}, {%8,%9}, {%0,%1,%2,%3};"
        : "+f"(c[0]), "+f"(c[1]), "+f"(c[2]), "+f"(c[3])
        : "r"(a0), "r"(a1), "r"(a2), "r"(a3), "r"(b0), "r"(b1));
}

// ---------------------------------------------------------------------------
// Kernel 0: dec_proj[b,n] = sum_d dec_state[b,d] * W_dec[d,n]
// ---------------------------------------------------------------------------
__global__ __launch_bounds__(256) void dec_proj_kernel(const float* __restrict__ dec_state,
                                                       const float* __restrict__ W_dec) {
    int b = blockIdx.x;
    int n = threadIdx.x;
    __shared__ float ds[ENCd];
    for (int i = threadIdx.x; i < ENCd; i += 256) ds[i] = dec_state[b * ENCd + i];
    __syncthreads();
    float acc = 0.f;
#pragma unroll 8
    for (int d = 0; d < ENCd; d++) acc += ds[d] * W_dec[d * ATTNd + n];
    g_dec_proj[b * ATTNd + n] = acc;
}

// ---------------------------------------------------------------------------
// Kernel 1: scores — TF32 mma, register-prefetch double buffering on the K loop
// ---------------------------------------------------------------------------
__global__ __launch_bounds__(256, 1) void scores_kernel(const float* __restrict__ enc,
                                                        const float* __restrict__ W_enc,
                                                        const float* __restrict__ v) {
    __shared__ uint32_t Asm[TILE_S * A_STRIDE];
    __shared__ uint32_t Bsm[KC * B_STRIDE];
    __shared__ float dp_sm[ATTNd];
    __shared__ float v_sm[ATTNd];
    __shared__ float red[TILE_S * 4];

    const int tid = threadIdx.x;
    const int b = blockIdx.y;
    const int s0 = blockIdx.x * TILE_S;
    const int warp = tid >> 5, lane = tid & 31;
    const int gid = lane >> 2, tig = lane & 3;
    const int warp_m = warp >> 2, warp_n = warp & 3;
    const int m_base = warp_m * 64, n_base = warp_n * 64;

    dp_sm[tid] = g_dec_proj[b * ATTNd + tid];
    v_sm[tid] = v[tid];

    float acc[4][8][4];
#pragma unroll
    for (int mt = 0; mt < 4; mt++)
#pragma unroll
        for (int nt = 0; nt < 8; nt++)
#pragma unroll
            for (int i = 0; i < 4; i++) acc[mt][nt][i] = 0.f;

    const float* encb = enc + ((size_t)b * Ssz + s0) * ENCd;

    // Staging index split (identical mapping to round 1)
    const int arow = tid >> 2, akq = tid & 3;      // A: rows arow, arow+64
    const int bkr = tid >> 6, bcq = tid & 63;      // B: k-rows bkr+4i

    float4 pa[2], pb[4];
    // Prefetch chunk 0
    pa[0] = *reinterpret_cast<const float4*>(encb + (size_t)arow * ENCd + akq * 4);
    pa[1] = *reinterpret_cast<const float4*>(encb + (size_t)(arow + 64) * ENCd + akq * 4);
#pragma unroll
    for (int i = 0; i < 4; i++)
        pb[i] = *reinterpret_cast<const float4*>(W_enc + (size_t)(bkr + 4 * i) * ATTNd + bcq * 4);

    for (int k0 = 0; k0 < ENCd; k0 += KC) {
        __syncthreads();   // previous chunk's MMAs done -> safe to overwrite smem
        // Store prefetched chunk (convert to tf32 here)
        {
            uint4 u;
            u.x = f2tf32(pa[0].x); u.y = f2tf32(pa[0].y); u.z = f2tf32(pa[0].z); u.w = f2tf32(pa[0].w);
            *reinterpret_cast<uint4*>(&Asm[arow * A_STRIDE + akq * 4]) = u;
            u.x = f2tf32(pa[1].x); u.y = f2tf32(pa[1].y); u.z = f2tf32(pa[1].z); u.w = f2tf32(pa[1].w);
            *reinterpret_cast<uint4*>(&Asm[(arow + 64) * A_STRIDE + akq * 4]) = u;
#pragma unroll
            for (int i = 0; i < 4; i++) {
                u.x = f2tf32(pb[i].x); u.y = f2tf32(pb[i].y); u.z = f2tf32(pb[i].z); u.w = f2tf32(pb[i].w);
                *reinterpret_cast<uint4*>(&Bsm[(bkr + 4 * i) * B_STRIDE + bcq * 4]) = u;
            }
        }
        __syncthreads();

        // Prefetch next chunk (overlaps with MMA below)
        int kn = k0 + KC;
        if (kn < ENCd) {
            pa[0] = *reinterpret_cast<const float4*>(encb + (size_t)arow * ENCd + kn + akq * 4);
            pa[1] = *reinterpret_cast<const float4*>(encb + (size_t)(arow + 64) * ENCd + kn + akq * 4);
#pragma unroll
            for (int i = 0; i < 4; i++)
                pb[i] = *reinterpret_cast<const float4*>(W_enc + (size_t)(kn + bkr + 4 * i) * ATTNd + bcq * 4);
        }

#pragma unroll
        for (int kk = 0; kk < KC; kk += 8) {
            uint32_t bf[8][2];
#pragma unroll
            for (int nt = 0; nt < 8; nt++) {
                int n = n_base + nt * 8 + gid;
                bf[nt][0] = Bsm[(kk + tig) * B_STRIDE + n];
                bf[nt][1] = Bsm[(kk + tig + 4) * B_STRIDE + n];
            }
#pragma unroll
            for (int mt = 0; mt < 4; mt++) {
                int r = m_base + mt * 16 + gid;
                uint32_t a0 = Asm[r * A_STRIDE + kk + tig];
                uint32_t a1 = Asm[(r + 8) * A_STRIDE + kk + tig];
                uint32_t a2 = Asm[r * A_STRIDE + kk + tig + 4];
                uint32_t a3 = Asm[(r + 8) * A_STRIDE + kk + tig + 4];
#pragma unroll
                for (int nt = 0; nt < 8; nt++)
                    mma_tf32(acc[mt][nt], a0, a1, a2, a3, bf[nt][0], bf[nt][1]);
            }
        }
    }

    // Epilogue: tanh(acc + dec_proj) * v, reduce over N
    float rowsum[8];
#pragma unroll
    for (int i = 0; i < 8; i++) rowsum[i] = 0.f;
#pragma unroll
    for (int mt = 0; mt < 4; mt++)
#pragma unroll
        for (int nt = 0; nt < 8; nt++) {
            int c0 = n_base + nt * 8 + tig * 2;
#pragma unroll
            for (int i = 0; i < 2; i++)
#pragma unroll
                for (int j = 0; j < 2; j++) {
                    int col = c0 + j;
                    rowsum[mt * 2 + i] +=
                        tanhf(acc[mt][nt][i * 2 + j] + dp_sm[col]) * v_sm[col];
                }
        }
#pragma unroll
    for (int i = 0; i < 8; i++) {
        rowsum[i] += __shfl_xor_sync(0xffffffff, rowsum[i], 1);
        rowsum[i] += __shfl_xor_sync(0xffffffff, rowsum[i], 2);
    }
    __syncthreads();
    if (tig == 0) {
#pragma unroll
        for (int mt = 0; mt < 4; mt++)
#pragma unroll
            for (int i = 0; i < 2; i++) {
                int row = m_base + mt * 16 + gid + 8 * i;
                red[row * 4 + warp_n] = rowsum[mt * 2 + i];
            }
    }
    __syncthreads();
    if (tid < TILE_S) {
        float s = red[tid * 4] + red[tid * 4 + 1] + red[tid * 4 + 2] + red[tid * 4 + 3];
        g_scores[b * Ssz + s0 + tid] = s;
    }
}

// ---------------------------------------------------------------------------
// Kernel 2: softmax over S per batch row -> attn region of d_out
// ---------------------------------------------------------------------------
__global__ __launch_bounds__(256) void softmax_kernel(float* __restrict__ attn_out) {
    int b = blockIdx.x;
    int tid = threadIdx.x;
    __shared__ float rbuf[256];

    float vals[8];
    float lmax = -1e30f;
#pragma unroll
    for (int i = 0; i < 8; i++) {
        float x = g_scores[b * Ssz + tid + i * 256];
        vals[i] = x;
        lmax = fmaxf(lmax, x);
    }
    rbuf[tid] = lmax;
    __syncthreads();
    for (int off = 128; off; off >>= 1) {
        if (tid < off) rbuf[tid] = fmaxf(rbuf[tid], rbuf[tid + off]);
        __syncthreads();
    }
    float m = rbuf[0];
    __syncthreads();

    float lsum = 0.f;
#pragma unroll
    for (int i = 0; i < 8; i++) {
        float e = expf(vals[i] - m);
        vals[i] = e;
        lsum += e;
    }
    rbuf[tid] = lsum;
    __syncthreads();
    for (int off = 128; off; off >>= 1) {
        if (tid < off) rbuf[tid] += rbuf[tid + off];
        __syncthreads();
    }
    float inv = 1.f / rbuf[0];
#pragma unroll
    for (int i = 0; i < 8; i++)
        attn_out[b * Ssz + tid + i * 256] = vals[i] * inv;
}

// ---------------------------------------------------------------------------
// Kernel 3a: context partials — split S across CSPLIT chunks, float4 columns
// grid (Bsz, CSPLIT), 128 threads; each CTA streams 128 rows x 512 cols.
// ---------------------------------------------------------------------------
__global__ __launch_bounds__(128) void context_part_kernel(const float* __restrict__ enc,
                                                           const float* __restrict__ attn) {
    const int SCHUNK = Ssz / CSPLIT;   // 128
    int b = blockIdx.x;
    int split = blockIdx.y;
    int e4 = threadIdx.x;              // float4 column 0..127

    __shared__ float wsm[SCHUNK];
    wsm[threadIdx.x] = attn[b * Ssz + split * SCHUNK + threadIdx.x];
    __syncthreads();

    const float* encb = enc + ((size_t)b * Ssz + split * SCHUNK) * ENCd;
    float4 acc = make_float4(0.f, 0.f, 0.f, 0.f);
#pragma unroll 8
    for (int s = 0; s < SCHUNK; s++) {
        float w = wsm[s];
        float4 x = *reinterpret_cast<const float4*>(encb + (size_t)s * ENCd + e4 * 4);
        acc.x += w * x.x; acc.y += w * x.y; acc.z += w * x.z; acc.w += w * x.w;
    }
    *reinterpret_cast<float4*>(&g_ctx_part[((size_t)split * Bsz + b) * ENCd + e4 * 4]) = acc;
}

// ---------------------------------------------------------------------------
// Kernel 3b: reduce partials -> ctx region of d_out
// ---------------------------------------------------------------------------
__global__ __launch_bounds__(256) void context_reduce_kernel(float* __restrict__ ctx_out) {
    int i = blockIdx.x * 256 + threadIdx.x;   // 0 .. 64*512-1
    float s = 0.f;
#pragma unroll
    for (int p = 0; p < CSPLIT; p++) s += g_ctx_part[(size_t)p * Bsz * ENCd + i];
    ctx_out[i] = s;
}

// ---------------------------------------------------------------------------
extern "C" void kernel_launch(void* const* d_in, const int* in_sizes, int n_in,
                              void* d_out, int out_size) {
    const float* enc       = (const float*)d_in[0];
    const float* dec_state = (const float*)d_in[1];
    const float* W_enc     = (const float*)d_in[2];
    const float* W_dec     = (const float*)d_in[3];
    const float* v         = (const float*)d_in[4];

    float* out  = (float*)d_out;
    float* ctx  = out;                   // [64,512]
    float* attn = out + Bsz * ENCd;      // [64,2048]

    dec_proj_kernel<<<Bsz, 256>>>(dec_state, W_dec);

    dim3 g1(Ssz / TILE_S, Bsz);
    scores_kernel<<<g1, 256>>>(enc, W_enc, v);

    softmax_kernel<<<Bsz, 256>>>(attn);

    dim3 g3(Bsz, CSPLIT);
    context_part_kernel<<<g3, 128>>>(enc, attn);

    context_reduce_kernel<<<(Bsz * ENCd) / 256, 256>>>(ctx);
}

// round 4
// speedup vs baseline: 2.2102x; 1.5333x over previous
#include <cuda_runtime.h>
#include <cuda_fp16.h>
#include <math.h>
#include <stdint.h>

#define Bsz   64
#define Ssz   2048
#define ENCd  512
#define ATTNd 256

#define TILE_S 128
#define KC     64                    // k per chunk
#define NCHUNK (ENCd / KC)           // 8
#define ABYTES (TILE_S * 128)        // 16384 (128 rows x 128B fp16)
#define BBYTES (ATTNd * 128)         // 32768

// smem offsets
#define SM_DP   0
#define SM_V    1024
#define SM_RED  2048
#define SM_A0   4096
#define SM_B0   (SM_A0 + 2 * ABYTES)          // 36864
#define SM_TOTAL (SM_B0 + 2 * BBYTES)         // 102400

#define CSPLIT 16

__device__ float  g_dec_proj[Bsz * ATTNd];
__device__ float  g_scores[Bsz * Ssz];
__device__ float  g_ctx_part[CSPLIT * Bsz * ENCd];
__device__ __half g_Bh[ENCd * ATTNd];          // pre-swizzled fp16 W_enc^T image

// ---------------------------------------------------------------------------
// helpers
// ---------------------------------------------------------------------------
__device__ __forceinline__ float tanh_fast(float x) {
    float y;
    asm("tanh.approx.f32 %0, %1;" : "=f"(y) : "f"(x));
    return y;
}
__device__ __forceinline__ uint32_t smem_u32(const void* p) {
    uint32_t a;
    asm("{ .reg .u64 t; cvta.to.shared.u64 t, %1; cvt.u32.u64 %0, t; }" : "=r"(a) : "l"(p));
    return a;
}
__device__ __forceinline__ uint32_t pack_h2(float lo, float hi) {
    uint32_t r;
    asm("cvt.rn.f16x2.f32 %0, %1, %2;" : "=r"(r) : "f"(hi), "f"(lo));
    return r;
}
__device__ __forceinline__ void cp_async16(uint32_t dst, const void* src) {
    asm volatile("cp.async.cg.shared.global [%0], [%1], 16;" :: "r"(dst), "l"(src));
}
#define CP_COMMIT() asm volatile("cp.async.commit_group;" ::: "memory")

__device__ __forceinline__ void ldsm_x4(uint32_t* r, uint32_t addr) {
    asm volatile("ldmatrix.sync.aligned.m8n8.x4.shared.b16 {%0,%1,%2,%3}, [%4];"
                 : "=r"(r[0]), "=r"(r[1]), "=r"(r[2]), "=r"(r[3]) : "r"(addr));
}
__device__ __forceinline__ void mma_f16(float c[4], const uint32_t a[4],
                                        uint32_t b0, uint32_t b1) {
    asm volatile(
        "mma.sync.aligned.m16n8k16.row.col.f32.f16.f16.f32 "
        "{%0,%1,%2,%3}, {%4,%5,%6,%7}, {%8,%9}, {%0,%1,%2,%3};"
        : "+f"(c[0]), "+f"(c[1]), "+f"(c[2]), "+f"(c[3])
        : "r"(a[0]), "r"(a[1]), "r"(a[2]), "r"(a[3]), "r"(b0), "r"(b1));
}

// ---------------------------------------------------------------------------
// Kernel P: pre-swizzled fp16 image of B: rows n (128B = 64 halves of k),
// SW128 swizzle baked: 16B-chunk j -> j ^ (n&7). Per k-chunk c (64 k's).
// ---------------------------------------------------------------------------
__global__ __launch_bounds__(256) void prep_bh_kernel(const float* __restrict__ W_enc) {
    int idx = blockIdx.x * 256 + threadIdx.x;   // 0 .. 512*256-1, k-major
    int k = idx >> 8, n = idx & 255;
    int c = k >> 6, j = (k >> 3) & 7, w = k & 7;
    int phys = j ^ (n & 7);
    g_Bh[(((size_t)c * 256 + n) * 8 + phys) * 8 + w] = __float2half_rn(W_enc[idx]);
}

// ---------------------------------------------------------------------------
// Kernel 0: dec_proj
// ---------------------------------------------------------------------------
__global__ __launch_bounds__(256) void dec_proj_kernel(const float* __restrict__ dec_state,
                                                       const float* __restrict__ W_dec) {
    int b = blockIdx.x;
    int n = threadIdx.x;
    __shared__ float ds[ENCd];
    for (int i = threadIdx.x; i < ENCd; i += 256) ds[i] = dec_state[b * ENCd + i];
    __syncthreads();
    float acc = 0.f;
#pragma unroll 8
    for (int d = 0; d < ENCd; d++) acc += ds[d] * W_dec[d * ATTNd + n];
    g_dec_proj[b * ATTNd + n] = acc;
}

// ---------------------------------------------------------------------------
// Kernel 1: scores via fp16 mma.sync m16n8k16 + ldmatrix, double-buffered
// CTA tile 128(S) x 256(N), K=512 in 8 chunks of 64.
// ---------------------------------------------------------------------------
__global__ __launch_bounds__(256) void scores_kernel(const float* __restrict__ enc,
                                                     const float* __restrict__ v) {
    extern __shared__ __align__(1024) char sm[];
    const uint32_t smb = smem_u32(sm);
    const int tid = threadIdx.x, wid = tid >> 5, lane = tid & 31;
    const int b = blockIdx.y, s0 = blockIdx.x * TILE_S;
    const int gid = lane >> 2, tig = lane & 3;
    const int warp_m = wid >> 2, warp_n = wid & 3;
    const int m_base = warp_m * 64, n_base = warp_n * 64;

    float* dp_sm = (float*)(sm + SM_DP);
    float* v_sm  = (float*)(sm + SM_V);
    float* red   = (float*)(sm + SM_RED);

    dp_sm[tid] = g_dec_proj[b * ATTNd + tid];
    v_sm[tid]  = v[tid];

    float acc[4][8][4];
#pragma unroll
    for (int mt = 0; mt < 4; mt++)
#pragma unroll
        for (int nt = 0; nt < 8; nt++)
#pragma unroll
            for (int i = 0; i < 4; i++) acc[mt][nt][i] = 0.f;

    const float* encb = enc + ((size_t)b * Ssz + s0) * ENCd;

    // ldmatrix address invariants
    const int lane15 = lane & 15;
    const int l16 = lane >> 4;                 // A k-chunk select
    int a_rowrel[4], a_rx[4];
#pragma unroll
    for (int mt = 0; mt < 4; mt++) {
        int r = m_base + mt * 16 + lane15;
        a_rowrel[mt] = r * 128;
        a_rx[mt] = r & 7;
    }
    const int b_lrow = (lane & 7) + ((lane >> 4) & 1) * 8;
    const int b_co = (lane >> 3) & 1;          // B k-chunk select
    int b_rowrel[4], b_rx[4];
#pragma unroll
    for (int pr = 0; pr < 4; pr++) {
        int r = n_base + pr * 16 + b_lrow;
        b_rowrel[pr] = r * 128;
        b_rx[pr] = r & 7;
    }

    // A staging mapping: thread -> row = tid>>1, k-half = tid&1 (32 k's)
    const int arow = tid >> 1, kh = tid & 1, arx = arow & 7;
    const float* asrc = encb + (size_t)arow * ENCd + kh * 32;
    char* const abase = sm + SM_A0 + arow * 128;

    float4 pa[8];
#define LDG_A(c_) do {                                                         \
        const float* p_ = asrc + (c_) * KC;                                    \
        _Pragma("unroll")                                                      \
        for (int q_ = 0; q_ < 8; q_++)                                         \
            pa[q_] = *reinterpret_cast<const float4*>(p_ + q_ * 4);            \
    } while (0)

#define STS_A(st_) do {                                                        \
        char* ab_ = abase + (st_) * ABYTES;                                    \
        _Pragma("unroll")                                                      \
        for (int i_ = 0; i_ < 4; i_++) {                                       \
            uint4 u_;                                                          \
            u_.x = pack_h2(pa[2 * i_].x, pa[2 * i_].y);                        \
            u_.y = pack_h2(pa[2 * i_].z, pa[2 * i_].w);                        \
            u_.z = pack_h2(pa[2 * i_ + 1].x, pa[2 * i_ + 1].y);                \
            u_.w = pack_h2(pa[2 * i_ + 1].z, pa[2 * i_ + 1].w);                \
            *reinterpret_cast<uint4*>(ab_ + (((kh * 4 + i_) ^ arx) << 4)) = u_;\
        }                                                                      \
    } while (0)

#define CPA_B(c_, st_) do {                                                    \
        uint32_t bd_ = smb + SM_B0 + (st_) * BBYTES;                           \
        const char* bs_ = (const char*)g_Bh + (size_t)(c_) * BBYTES;           \
        _Pragma("unroll")                                                      \
        for (int i_ = 0; i_ < 8; i_++) {                                       \
            int q_ = tid + i_ * 256;                                           \
            cp_async16(bd_ + q_ * 16, bs_ + q_ * 16);                          \
        }                                                                      \
        CP_COMMIT();                                                           \
    } while (0)

    // prologue
    LDG_A(0);
    CPA_B(0, 0);

    for (int c = 0; c < NCHUNK; c++) {
        const int st = c & 1;
        STS_A(st);                                  // safe: Ast[st] last read at chunk c-2
        asm volatile("cp.async.wait_group 0;" ::: "memory");
        __syncthreads();                            // A(c) stored, B(c) landed, all warps past MMA(c-1)

        if (c + 1 < NCHUNK) {
            CPA_B(c + 1, st ^ 1);                   // overlaps with MMA below
            LDG_A(c + 1);
        }

        const uint32_t Au = smb + SM_A0 + st * ABYTES;
        const uint32_t Bu = smb + SM_B0 + st * BBYTES;
#pragma unroll
        for (int kk = 0; kk < 4; kk++) {
            uint32_t af[4][4], bf[4][4];
#pragma unroll
            for (int mt = 0; mt < 4; mt++)
                ldsm_x4(af[mt], Au + a_rowrel[mt] + (((2 * kk + l16) ^ a_rx[mt]) << 4));
#pragma unroll
            for (int pr = 0; pr < 4; pr++)
                ldsm_x4(bf[pr], Bu + b_rowrel[pr] + (((2 * kk + b_co) ^ b_rx[pr]) << 4));
#pragma unroll
            for (int mt = 0; mt < 4; mt++)
#pragma unroll
                for (int nt = 0; nt < 8; nt++) {
                    int pr = nt >> 1, bi = (nt & 1) * 2;
                    mma_f16(acc[mt][nt], af[mt], bf[pr][bi], bf[pr][bi + 1]);
                }
        }
    }
#undef LDG_A
#undef STS_A
#undef CPA_B

    // Epilogue: rowsum over N of tanh(D + dec_proj) * v
    float rowsum[8];
#pragma unroll
    for (int i = 0; i < 8; i++) rowsum[i] = 0.f;
#pragma unroll
    for (int mt = 0; mt < 4; mt++)
#pragma unroll
        for (int nt = 0; nt < 8; nt++) {
            int c0 = n_base + nt * 8 + tig * 2;
#pragma unroll
            for (int i = 0; i < 2; i++)
#pragma unroll
                for (int j = 0; j < 2; j++) {
                    int col = c0 + j;
                    rowsum[mt * 2 + i] +=
                        tanh_fast(acc[mt][nt][i * 2 + j] + dp_sm[col]) * v_sm[col];
                }
        }
#pragma unroll
    for (int i = 0; i < 8; i++) {
        rowsum[i] += __shfl_xor_sync(0xffffffff, rowsum[i], 1);
        rowsum[i] += __shfl_xor_sync(0xffffffff, rowsum[i], 2);
    }
    __syncthreads();
    if (tig == 0) {
#pragma unroll
        for (int mt = 0; mt < 4; mt++)
#pragma unroll
            for (int i = 0; i < 2; i++) {
                int row = m_base + mt * 16 + gid + 8 * i;
                red[row * 4 + warp_n] = rowsum[mt * 2 + i];
            }
    }
    __syncthreads();
    if (tid < TILE_S) {
        float s = red[tid * 4] + red[tid * 4 + 1] + red[tid * 4 + 2] + red[tid * 4 + 3];
        g_scores[b * Ssz + s0 + tid] = s;
    }
}

// ---------------------------------------------------------------------------
// Kernel 2: softmax
// ---------------------------------------------------------------------------
__global__ __launch_bounds__(256) void softmax_kernel(float* __restrict__ attn_out) {
    int b = blockIdx.x;
    int tid = threadIdx.x;
    __shared__ float rbuf[256];

    float vals[8];
    float lmax = -1e30f;
#pragma unroll
    for (int i = 0; i < 8; i++) {
        float x = g_scores[b * Ssz + tid + i * 256];
        vals[i] = x;
        lmax = fmaxf(lmax, x);
    }
    rbuf[tid] = lmax;
    __syncthreads();
    for (int off = 128; off; off >>= 1) {
        if (tid < off) rbuf[tid] = fmaxf(rbuf[tid], rbuf[tid + off]);
        __syncthreads();
    }
    float mx = rbuf[0];
    __syncthreads();

    float lsum = 0.f;
#pragma unroll
    for (int i = 0; i < 8; i++) {
        float e = expf(vals[i] - mx);
        vals[i] = e;
        lsum += e;
    }
    rbuf[tid] = lsum;
    __syncthreads();
    for (int off = 128; off; off >>= 1) {
        if (tid < off) rbuf[tid] += rbuf[tid + off];
        __syncthreads();
    }
    float inv = 1.f / rbuf[0];
#pragma unroll
    for (int i = 0; i < 8; i++)
        attn_out[b * Ssz + tid + i * 256] = vals[i] * inv;
}

// ---------------------------------------------------------------------------
// Kernel 3a/3b: context (split-S partials + reduce)
// ---------------------------------------------------------------------------
__global__ __launch_bounds__(128) void context_part_kernel(const float* __restrict__ enc,
                                                           const float* __restrict__ attn) {
    const int SCHUNK = Ssz / CSPLIT;   // 128
    int b = blockIdx.x;
    int split = blockIdx.y;
    int e4 = threadIdx.x;

    __shared__ float wsm[128];
    wsm[threadIdx.x] = attn[b * Ssz + split * SCHUNK + threadIdx.x];
    __syncthreads();

    const float* encb = enc + ((size_t)b * Ssz + split * SCHUNK) * ENCd;
    float4 acc = make_float4(0.f, 0.f, 0.f, 0.f);
#pragma unroll 8
    for (int s = 0; s < SCHUNK; s++) {
        float w = wsm[s];
        float4 x = *reinterpret_cast<const float4*>(encb + (size_t)s * ENCd + e4 * 4);
        acc.x += w * x.x; acc.y += w * x.y; acc.z += w * x.z; acc.w += w * x.w;
    }
    *reinterpret_cast<float4*>(&g_ctx_part[((size_t)split * Bsz + b) * ENCd + e4 * 4]) = acc;
}

__global__ __launch_bounds__(256) void context_reduce_kernel(float* __restrict__ ctx_out) {
    int i = blockIdx.x * 256 + threadIdx.x;
    float s = 0.f;
#pragma unroll
    for (int p = 0; p < CSPLIT; p++) s += g_ctx_part[(size_t)p * Bsz * ENCd + i];
    ctx_out[i] = s;
}

// ---------------------------------------------------------------------------
extern "C" void kernel_launch(void* const* d_in, const int* in_sizes, int n_in,
                              void* d_out, int out_size) {
    const float* enc       = (const float*)d_in[0];
    const float* dec_state = (const float*)d_in[1];
    const float* W_enc     = (const float*)d_in[2];
    const float* W_dec     = (const float*)d_in[3];
    const float* v         = (const float*)d_in[4];

    float* out  = (float*)d_out;
    float* ctx  = out;
    float* attn = out + Bsz * ENCd;

    cudaFuncSetAttribute(scores_kernel,
                         cudaFuncAttributeMaxDynamicSharedMemorySize, SM_TOTAL);

    prep_bh_kernel<<<(ENCd * ATTNd) / 256, 256>>>(W_enc);
    dec_proj_kernel<<<Bsz, 256>>>(dec_state, W_dec);

    dim3 g1(Ssz / TILE_S, Bsz);
    scores_kernel<<<g1, 256, SM_TOTAL>>>(enc, v);

    softmax_kernel<<<Bsz, 256>>>(attn);

    dim3 g3(Bsz, CSPLIT);
    context_part_kernel<<<g3, 128>>>(enc, attn);
    context_reduce_kernel<<<(Bsz * ENCd) / 256, 256>>>(ctx);
}